// round 1
// baseline (speedup 1.0000x reference)
#include <cuda_runtime.h>

// Problem constants
#define NN   8192   // rows/cols of A, rows of X
#define CD   128    // feature columns (64 node + 64 edge)
#define HALFC 64

// Scratch (static device globals: allocation-guard safe)
__device__ __align__(16) float g_X0[NN * CD];
__device__ __align__(16) float g_X1[NN * CD];

// ---------------------------------------------------------------------------
// Pack [F | new_features] -> g_X0  (row-major [NN, 128])
// ---------------------------------------------------------------------------
__global__ void pack_kernel(const float* __restrict__ F,
                            const float* __restrict__ G)
{
    int idx = blockIdx.x * blockDim.x + threadIdx.x;   // over NN*64
    if (idx < NN * HALFC) {
        int row = idx >> 6;
        int col = idx & 63;
        g_X0[row * CD + col]          = F[idx];
        g_X0[row * CD + HALFC + col]  = G[idx];
    }
}

// ---------------------------------------------------------------------------
// C[8192,128] = A[8192,8192] @ B[8192,128], ReLU on cols [0,64)
// Tiles: BM=64, BN=128, BK=16. 256 threads, 8x4 per-thread microtile.
// Double-buffered shared memory, register prefetch of the next K-tile.
// mode==0: B = g_X0, C = g_X1      (layer 1)
// mode==1: B = g_X1, C = Cout      (layer 2 -> d_out)
// ---------------------------------------------------------------------------
__global__ __launch_bounds__(256, 1)
void gemm_relu_kernel(const float* __restrict__ A, int mode, float* __restrict__ Cout)
{
    const int BM = 64, BN = 128, BK = 16;
    const float* __restrict__ B = (mode == 0) ? g_X0 : g_X1;
    float* __restrict__ C       = (mode == 0) ? g_X1 : Cout;

    __shared__ __align__(16) float As[2][BK][BM];   // A tile, transposed (k-major)
    __shared__ __align__(16) float Bs[2][BK][BN];   // B tile, as-is

    const int tid = threadIdx.x;
    const int tx  = tid & 31;    // 0..31 -> column group (4 cols each)
    const int ty  = tid >> 5;    // 0..7  -> row group (8 rows each)
    const int bm  = blockIdx.x;  // 0..127

    // A-tile load mapping: one float4 per thread (64 rows x 16 cols = 256 float4)
    const int aRow  = tid >> 2;        // 0..63
    const int aCol4 = (tid & 3) * 4;   // 0,4,8,12
    // B-tile load mapping: two float4 per thread (16 rows x 128 cols = 512 float4)
    const int bRow = tid >> 5;         // 0..7 (and +8)
    const int bCol = (tid & 31) * 4;   // 0..124

    const float* Arow = A + (size_t)(bm * BM + aRow) * NN + aCol4;

    float acc[8][4];
#pragma unroll
    for (int i = 0; i < 8; ++i)
#pragma unroll
        for (int j = 0; j < 4; ++j) acc[i][j] = 0.0f;

    // ---- preload K-tile 0 into registers ----
    float4 ra  = *reinterpret_cast<const float4*>(Arow);
    const float* bp0 = B + bRow * CD + bCol;
    float4 rb0 = *reinterpret_cast<const float4*>(bp0);
    float4 rb1 = *reinterpret_cast<const float4*>(bp0 + 8 * CD);

    int buf = 0;
    // store tile 0 to shared
    As[buf][aCol4 + 0][aRow] = ra.x;
    As[buf][aCol4 + 1][aRow] = ra.y;
    As[buf][aCol4 + 2][aRow] = ra.z;
    As[buf][aCol4 + 3][aRow] = ra.w;
    *reinterpret_cast<float4*>(&Bs[buf][bRow][bCol])     = rb0;
    *reinterpret_cast<float4*>(&Bs[buf][bRow + 8][bCol]) = rb1;
    __syncthreads();

    const int NT = NN / BK;   // 512 K-tiles
    for (int kt = 0; kt < NT; ++kt) {
        // prefetch next tile (GMEM -> regs) so latency overlaps compute
        if (kt + 1 < NT) {
            ra = *reinterpret_cast<const float4*>(Arow + (size_t)(kt + 1) * BK);
            const float* bp = B + (size_t)(kt + 1) * BK * CD + bRow * CD + bCol;
            rb0 = *reinterpret_cast<const float4*>(bp);
            rb1 = *reinterpret_cast<const float4*>(bp + 8 * CD);
        }

        // compute on current buffer
#pragma unroll
        for (int kk = 0; kk < BK; ++kk) {
            float4 b0 = *reinterpret_cast<const float4*>(&Bs[buf][kk][tx * 4]);
            float4 a0 = *reinterpret_cast<const float4*>(&As[buf][kk][ty * 8]);
            float4 a1 = *reinterpret_cast<const float4*>(&As[buf][kk][ty * 8 + 4]);
            float av[8] = {a0.x, a0.y, a0.z, a0.w, a1.x, a1.y, a1.z, a1.w};
            float bv[4] = {b0.x, b0.y, b0.z, b0.w};
#pragma unroll
            for (int i = 0; i < 8; ++i)
#pragma unroll
                for (int j = 0; j < 4; ++j)
                    acc[i][j] = fmaf(av[i], bv[j], acc[i][j]);
        }

        // store prefetched tile into the other buffer
        if (kt + 1 < NT) {
            int nb = buf ^ 1;
            As[nb][aCol4 + 0][aRow] = ra.x;
            As[nb][aCol4 + 1][aRow] = ra.y;
            As[nb][aCol4 + 2][aRow] = ra.z;
            As[nb][aCol4 + 3][aRow] = ra.w;
            *reinterpret_cast<float4*>(&Bs[nb][bRow][bCol])     = rb0;
            *reinterpret_cast<float4*>(&Bs[nb][bRow + 8][bCol]) = rb1;
            __syncthreads();
            buf = nb;
        }
    }

    // ---- epilogue: fused ReLU on columns [0,64) ----
    const bool doRelu = (tx * 4) < HALFC;  // thread's 4 cols are entirely in one half
#pragma unroll
    for (int i = 0; i < 8; ++i) {
        int row = bm * BM + ty * 8 + i;
        float4 o;
        o.x = acc[i][0]; o.y = acc[i][1]; o.z = acc[i][2]; o.w = acc[i][3];
        if (doRelu) {
            o.x = fmaxf(o.x, 0.0f);
            o.y = fmaxf(o.y, 0.0f);
            o.z = fmaxf(o.z, 0.0f);
            o.w = fmaxf(o.w, 0.0f);
        }
        *reinterpret_cast<float4*>(C + (size_t)row * CD + tx * 4) = o;
    }
}

// ---------------------------------------------------------------------------
// kernel_launch: pack -> layer1 GEMM -> layer2 GEMM (all graph-capturable)
// inputs: d_in[0]=A [8192*8192], d_in[1]=F [8192*64], d_in[2]=new [8192*64]
// ---------------------------------------------------------------------------
extern "C" void kernel_launch(void* const* d_in, const int* in_sizes, int n_in,
                              void* d_out, int out_size)
{
    const float* A = (const float*)d_in[0];
    const float* F = (const float*)d_in[1];
    const float* G = (const float*)d_in[2];
    float* out     = (float*)d_out;

    pack_kernel<<<(NN * HALFC + 255) / 256, 256>>>(F, G);
    gemm_relu_kernel<<<NN / 64, 256>>>(A, 0, out);   // layer 1: g_X0 -> g_X1
    gemm_relu_kernel<<<NN / 64, 256>>>(A, 1, out);   // layer 2: g_X1 -> d_out
}

// round 7
// speedup vs baseline: 1.4011x; 1.4011x over previous
#include <cuda_runtime.h>
#include <cuda_pipeline.h>
#include <cuda_bf16.h>

#define NN 8192
#define CD 128

#define BK 32
#define NITER 256
#define STAGES 3
#define STAGE_B 24576
#define OFF_ALO 4096
#define OFF_BHI 8192
#define OFF_BLO 16384
#define SMEM_TOTAL (STAGES * STAGE_B)

__device__ __nv_bfloat16 g_Ahi[(size_t)NN * NN];
__device__ __nv_bfloat16 g_Alo[(size_t)NN * NN];
__device__ __nv_bfloat16 g_Bhi[2][(size_t)CD * NN];
__device__ __nv_bfloat16 g_Blo[2][(size_t)CD * NN];
__device__ float g_Y[(size_t)NN * CD];

__device__ __forceinline__ void ldsm4(unsigned& r0, unsigned& r1, unsigned& r2, unsigned& r3, unsigned addr) {
    asm volatile("ldmatrix.sync.aligned.m8n8.x4.shared.b16 {%0, %1, %2, %3}, [%4];"
                 : "=r"(r0), "=r"(r1), "=r"(r2), "=r"(r3) : "r"(addr));
}
__device__ __forceinline__ void mma16816(float* c, unsigned a0, unsigned a1, unsigned a2, unsigned a3, unsigned b0, unsigned b1) {
    asm volatile("mma.sync.aligned.m16n8k16.row.col.f32.bf16.bf16.f32 {%0, %1, %2, %3}, {%4, %5, %6, %7}, {%8, %9}, {%0, %1, %2, %3};"
                 : "+f"(c[0]), "+f"(c[1]), "+f"(c[2]), "+f"(c[3])
                 : "r"(a0), "r"(a1), "r"(a2), "r"(a3), "r"(b0), "r"(b1));
}

__device__ __forceinline__ unsigned sw_off(int row, int chunk) {
    return (unsigned)(row * 64 + (chunk ^ ((row >> 1) & 3)) * 16);
}

__device__ __forceinline__ void split_bf16(float v, __nv_bfloat16& h, __nv_bfloat16& l) {
    h = __float2bfloat16_rn(v);
    l = __float2bfloat16_rn(v - __bfloat162float(h));
}
__device__ __forceinline__ unsigned pack_bf2(__nv_bfloat16 a, __nv_bfloat16 b) {
    unsigned lo = (unsigned)__bfloat16_as_ushort(a);
    unsigned hi = (unsigned)__bfloat16_as_ushort(b);
    return lo | (hi << 16);
}

__global__ __launch_bounds__(256) void convA_kernel(const float* __restrict__ A)
{
    const float4* A4 = (const float4*)A;
    uint2* H2 = (uint2*)g_Ahi;
    uint2* L2 = (uint2*)g_Alo;
    size_t n4 = (size_t)NN * NN / 4;
    size_t stride = (size_t)gridDim.x * blockDim.x;
    size_t j = (size_t)blockIdx.x * blockDim.x + threadIdx.x;
    for (; j < n4; j += stride) {
        float4 v = A4[j];
        __nv_bfloat16 h0, h1, h2, h3, l0, l1, l2, l3;
        split_bf16(v.x, h0, l0);
        split_bf16(v.y, h1, l1);
        split_bf16(v.z, h2, l2);
        split_bf16(v.w, h3, l3);
        uint2 wh;
        uint2 wl;
        wh.x = pack_bf2(h0, h1);
        wh.y = pack_bf2(h2, h3);
        wl.x = pack_bf2(l0, l1);
        wl.y = pack_bf2(l2, l3);
        H2[j] = wh;
        L2[j] = wl;
    }
}

__global__ __launch_bounds__(256) void packX_kernel(const float* __restrict__ F,
                                                    const float* __restrict__ G)
{
    int idx = blockIdx.x * blockDim.x + threadIdx.x;
    int col = idx >> 13;
    int row = idx & (NN - 1);
    float v;
    if (col < 64) v = F[row * 64 + col];
    else v = G[row * 64 + (col - 64)];
    __nv_bfloat16 h, l;
    split_bf16(v, h, l);
    g_Bhi[0][idx] = h;
    g_Blo[0][idx] = l;
}

__global__ __launch_bounds__(256) void packY_kernel()
{
    int idx = blockIdx.x * blockDim.x + threadIdx.x;
    int col = idx >> 13;
    int row = idx & (NN - 1);
    float v = g_Y[(size_t)row * CD + col];
    __nv_bfloat16 h, l;
    split_bf16(v, h, l);
    g_Bhi[1][idx] = h;
    g_Blo[1][idx] = l;
}

__device__ __forceinline__ void load_stage(char* smem, int s, int it, int tid, size_t arow0,
                                           const __nv_bfloat16* __restrict__ Bhi,
                                           const __nv_bfloat16* __restrict__ Blo)
{
    char* st = smem + s * STAGE_B;
    size_t k0 = (size_t)it * BK;

    int arow = tid >> 2;
    int achunk = tid & 3;
    unsigned aso = sw_off(arow, achunk);
    size_t aoff = (arow0 + arow) * NN + k0 + achunk * 8;
    __pipeline_memcpy_async(st + aso, g_Ahi + aoff, 16);
    __pipeline_memcpy_async(st + OFF_ALO + aso, g_Alo + aoff, 16);

    int i;
#pragma unroll
    for (i = 0; i < 2; ++i) {
        int u = tid + i * 256;
        int brow = u >> 2;
        int bchunk = u & 3;
        unsigned bso = sw_off(brow, bchunk);
        size_t boff = (size_t)brow * NN + k0 + bchunk * 8;
        __pipeline_memcpy_async(st + OFF_BHI + bso, Bhi + boff, 16);
        __pipeline_memcpy_async(st + OFF_BLO + bso, Blo + boff, 16);
    }
    __pipeline_commit();
}

__global__ __launch_bounds__(256) void gemm_kernel(int layer, float* __restrict__ out)
{
    extern __shared__ char smem[];
    const int tid = threadIdx.x;
    const int lane = tid & 31;
    const int warp = tid >> 5;
    const int wm = warp & 1;
    const int wn = warp >> 1;

    unsigned sbase = (unsigned)__cvta_generic_to_shared(smem);

    const __nv_bfloat16* Bhi = g_Bhi[layer];
    const __nv_bfloat16* Blo = g_Blo[layer];

    const size_t arow0 = (size_t)blockIdx.x * 64;

    float acc[2][4][4];
    int t, j, q;
#pragma unroll
    for (t = 0; t < 2; ++t)
#pragma unroll
        for (j = 0; j < 4; ++j)
#pragma unroll
            for (q = 0; q < 4; ++q) acc[t][j][q] = 0.0f;

    load_stage(smem, 0, 0, tid, arow0, Bhi, Blo);
    load_stage(smem, 1, 1, tid, arow0, Bhi, Blo);
    load_stage(smem, 2, 2, tid, arow0, Bhi, Blo);

    const int a_roff = lane & 15;
    const int a_coff = lane >> 4;
    const int b_m = lane >> 3;
    const int b_roff = ((b_m >> 1) * 8) + (lane & 7);
    const int b_coff = b_m & 1;

    for (int it = 0; it < NITER; ++it) {
        int s = it - (it / STAGES) * STAGES;
        __pipeline_wait_prior(2);
        __syncthreads();

        unsigned stb = sbase + s * STAGE_B;
        int ks;
#pragma unroll
        for (ks = 0; ks < 2; ++ks) {
            unsigned ah[2][4];
            unsigned al[2][4];
#pragma unroll
            for (t = 0; t < 2; ++t) {
                int row = wm * 32 + t * 16 + a_roff;
                int chunk = ks * 2 + a_coff;
                unsigned so = sw_off(row, chunk);
                ldsm4(ah[t][0], ah[t][1], ah[t][2], ah[t][3], stb + so);
                ldsm4(al[t][0], al[t][1], al[t][2], al[t][3], stb + OFF_ALO + so);
            }
            unsigned bh[4][2];
            unsigned bl[4][2];
            int p;
#pragma unroll
            for (p = 0; p < 2; ++p) {
                int row = wn * 32 + p * 16 + b_roff;
                int chunk = ks * 2 + b_coff;
                unsigned so = sw_off(row, chunk);
                unsigned r0, r1, r2, r3;
                ldsm4(r0, r1, r2, r3, stb + OFF_BHI + so);
                bh[p * 2][0] = r0;
                bh[p * 2][1] = r1;
                bh[p * 2 + 1][0] = r2;
                bh[p * 2 + 1][1] = r3;
                ldsm4(r0, r1, r2, r3, stb + OFF_BLO + so);
                bl[p * 2][0] = r0;
                bl[p * 2][1] = r1;
                bl[p * 2 + 1][0] = r2;
                bl[p * 2 + 1][1] = r3;
            }
#pragma unroll
            for (t = 0; t < 2; ++t) {
#pragma unroll
                for (j = 0; j < 4; ++j) {
                    mma16816(acc[t][j], ah[t][0], ah[t][1], ah[t][2], ah[t][3], bh[j][0], bh[j][1]);
                    mma16816(acc[t][j], ah[t][0], ah[t][1], ah[t][2], ah[t][3], bl[j][0], bl[j][1]);
                    mma16816(acc[t][j], al[t][0], al[t][1], al[t][2], al[t][3], bh[j][0], bh[j][1]);
                }
            }
        }

        __syncthreads();
        if (it + STAGES < NITER) {
            load_stage(smem, s, it + STAGES, tid, arow0, Bhi, Blo);
        } else {
            __pipeline_commit();
        }
    }

    float* dst = out;
    if (layer == 0) dst = (float*)g_Y;

    const int g = lane >> 2;
    const int tig = lane & 3;
#pragma unroll
    for (t = 0; t < 2; ++t) {
#pragma unroll
        for (j = 0; j < 4; ++j) {
            int col = wn * 32 + j * 8 + tig * 2;
            size_t row0 = arow0 + wm * 32 + t * 16 + g;
            size_t row1 = row0 + 8;
            float2 v0;
            float2 v1;
            v0.x = acc[t][j][0];
            v0.y = acc[t][j][1];
            v1.x = acc[t][j][2];
            v1.y = acc[t][j][3];
            if (col < 64) {
                v0.x = fmaxf(v0.x, 0.0f);
                v0.y = fmaxf(v0.y, 0.0f);
                v1.x = fmaxf(v1.x, 0.0f);
                v1.y = fmaxf(v1.y, 0.0f);
            }
            *reinterpret_cast<float2*>(dst + row0 * CD + col) = v0;
            *reinterpret_cast<float2*>(dst + row1 * CD + col) = v1;
        }
    }
}

extern "C" void kernel_launch(void* const* d_in, const int* in_sizes, int n_in,
                              void* d_out, int out_size)
{
    const float* A = (const float*)d_in[0];
    const float* F = (const float*)d_in[1];
    const float* G = (const float*)d_in[2];
    float* out = (float*)d_out;

    cudaFuncSetAttribute(gemm_kernel, cudaFuncAttributeMaxDynamicSharedMemorySize, SMEM_TOTAL);

    convA_kernel<<<2048, 256>>>(A);
    packX_kernel<<<(CD * NN) / 256, 256>>>(F, G);
    gemm_kernel<<<NN / 64, 256, SMEM_TOTAL>>>(0, out);
    packY_kernel<<<(CD * NN) / 256, 256>>>();
    gemm_kernel<<<NN / 64, 256, SMEM_TOTAL>>>(1, out);
}

// round 8
// speedup vs baseline: 2.0611x; 1.4711x over previous
#include <cuda_runtime.h>
#include <cuda_pipeline.h>
#include <cuda_bf16.h>

#define NN 8192
#define CD 128

#define BK 32
#define NITER 256
#define STAGES 5
#define STAGE_B 24576
#define OFF_ALO 4096
#define OFF_BHI 8192
#define OFF_BLO 16384
#define SMEM_TOTAL (STAGES * STAGE_B)

__device__ __nv_bfloat16 g_Ahi[(size_t)NN * NN];
__device__ __nv_bfloat16 g_Alo[(size_t)NN * NN];
__device__ __nv_bfloat16 g_Bhi[2][(size_t)CD * NN];
__device__ __nv_bfloat16 g_Blo[2][(size_t)CD * NN];
__device__ float g_Y[(size_t)NN * CD];

__device__ __forceinline__ void ldsm4(unsigned& r0, unsigned& r1, unsigned& r2, unsigned& r3, unsigned addr) {
    asm volatile("ldmatrix.sync.aligned.m8n8.x4.shared.b16 {%0, %1, %2, %3}, [%4];"
                 : "=r"(r0), "=r"(r1), "=r"(r2), "=r"(r3) : "r"(addr));
}
__device__ __forceinline__ void mma16816(float* c, unsigned a0, unsigned a1, unsigned a2, unsigned a3, unsigned b0, unsigned b1) {
    asm volatile("mma.sync.aligned.m16n8k16.row.col.f32.bf16.bf16.f32 {%0, %1, %2, %3}, {%4, %5, %6, %7}, {%8, %9}, {%0, %1, %2, %3};"
                 : "+f"(c[0]), "+f"(c[1]), "+f"(c[2]), "+f"(c[3])
                 : "r"(a0), "r"(a1), "r"(a2), "r"(a3), "r"(b0), "r"(b1));
}

__device__ __forceinline__ unsigned sw_off(int row, int chunk) {
    return (unsigned)(row * 64 + (chunk ^ ((row >> 1) & 3)) * 16);
}

__device__ __forceinline__ void split_bf16(float v, __nv_bfloat16& h, __nv_bfloat16& l) {
    h = __float2bfloat16_rn(v);
    l = __float2bfloat16_rn(v - __bfloat162float(h));
}
__device__ __forceinline__ unsigned pack_bf2(__nv_bfloat16 a, __nv_bfloat16 b) {
    unsigned lo = (unsigned)__bfloat16_as_ushort(a);
    unsigned hi = (unsigned)__bfloat16_as_ushort(b);
    return lo | (hi << 16);
}

__global__ __launch_bounds__(256) void convA_kernel(const float* __restrict__ A)
{
    const float4* A4 = (const float4*)A;
    uint2* H2 = (uint2*)g_Ahi;
    uint2* L2 = (uint2*)g_Alo;
    size_t n4 = (size_t)NN * NN / 4;
    size_t stride = (size_t)gridDim.x * blockDim.x;
    size_t j = (size_t)blockIdx.x * blockDim.x + threadIdx.x;
    for (; j < n4; j += stride) {
        float4 v = A4[j];
        __nv_bfloat16 h0, h1, h2, h3, l0, l1, l2, l3;
        split_bf16(v.x, h0, l0);
        split_bf16(v.y, h1, l1);
        split_bf16(v.z, h2, l2);
        split_bf16(v.w, h3, l3);
        uint2 wh;
        uint2 wl;
        wh.x = pack_bf2(h0, h1);
        wh.y = pack_bf2(h2, h3);
        wl.x = pack_bf2(l0, l1);
        wl.y = pack_bf2(l2, l3);
        H2[j] = wh;
        L2[j] = wl;
    }
}

__global__ __launch_bounds__(256) void packX_kernel(const float* __restrict__ F,
                                                    const float* __restrict__ G)
{
    int idx = blockIdx.x * blockDim.x + threadIdx.x;
    int col = idx >> 13;
    int row = idx & (NN - 1);
    float v;
    if (col < 64) v = F[row * 64 + col];
    else v = G[row * 64 + (col - 64)];
    __nv_bfloat16 h, l;
    split_bf16(v, h, l);
    g_Bhi[0][idx] = h;
    g_Blo[0][idx] = l;
}

__global__ __launch_bounds__(256) void packY_kernel()
{
    int idx = blockIdx.x * blockDim.x + threadIdx.x;
    int col = idx >> 13;
    int row = idx & (NN - 1);
    float v = g_Y[(size_t)row * CD + col];
    __nv_bfloat16 h, l;
    split_bf16(v, h, l);
    g_Bhi[1][idx] = h;
    g_Blo[1][idx] = l;
}

__device__ __forceinline__ void load_stage(char* smem, int s, int it, int tid, size_t arow0,
                                           const __nv_bfloat16* __restrict__ Bhi,
                                           const __nv_bfloat16* __restrict__ Blo)
{
    char* st = smem + s * STAGE_B;
    size_t k0 = (size_t)it * BK;

    int arow = tid >> 2;
    int achunk = tid & 3;
    unsigned aso = sw_off(arow, achunk);
    size_t aoff = (arow0 + arow) * NN + k0 + achunk * 8;
    __pipeline_memcpy_async(st + aso, g_Ahi + aoff, 16);
    __pipeline_memcpy_async(st + OFF_ALO + aso, g_Alo + aoff, 16);

    int i;
#pragma unroll
    for (i = 0; i < 2; ++i) {
        int u = tid + i * 256;
        int brow = u >> 2;
        int bchunk = u & 3;
        unsigned bso = sw_off(brow, bchunk);
        size_t boff = (size_t)brow * NN + k0 + bchunk * 8;
        __pipeline_memcpy_async(st + OFF_BHI + bso, Bhi + boff, 16);
        __pipeline_memcpy_async(st + OFF_BLO + bso, Blo + boff, 16);
    }
    __pipeline_commit();
}

__global__ __launch_bounds__(256) void gemm_kernel(int layer, float* __restrict__ out)
{
    extern __shared__ char smem[];
    const int tid = threadIdx.x;
    const int lane = tid & 31;
    const int warp = tid >> 5;
    const int wm = warp & 1;
    const int wn = warp >> 1;

    unsigned sbase = (unsigned)__cvta_generic_to_shared(smem);

    const __nv_bfloat16* Bhi = g_Bhi[layer];
    const __nv_bfloat16* Blo = g_Blo[layer];

    const size_t arow0 = (size_t)blockIdx.x * 64;

    float acc[2][4][4];
    int t, j, q;
#pragma unroll
    for (t = 0; t < 2; ++t)
#pragma unroll
        for (j = 0; j < 4; ++j)
#pragma unroll
            for (q = 0; q < 4; ++q) acc[t][j][q] = 0.0f;

    load_stage(smem, 0, 0, tid, arow0, Bhi, Blo);
    load_stage(smem, 1, 1, tid, arow0, Bhi, Blo);
    load_stage(smem, 2, 2, tid, arow0, Bhi, Blo);
    load_stage(smem, 3, 3, tid, arow0, Bhi, Blo);
    load_stage(smem, 4, 4, tid, arow0, Bhi, Blo);

    const int a_roff = lane & 15;
    const int a_coff = lane >> 4;
    const int b_m = lane >> 3;
    const int b_roff = ((b_m >> 1) * 8) + (lane & 7);
    const int b_coff = b_m & 1;

    for (int it = 0; it < NITER; ++it) {
        int s = it - (it / STAGES) * STAGES;
        __pipeline_wait_prior(STAGES - 1);
        __syncthreads();

        unsigned stb = sbase + s * STAGE_B;
        int ks;
#pragma unroll
        for (ks = 0; ks < 2; ++ks) {
            unsigned ah[2][4];
            unsigned al[2][4];
#pragma unroll
            for (t = 0; t < 2; ++t) {
                int row = wm * 32 + t * 16 + a_roff;
                int chunk = ks * 2 + a_coff;
                unsigned so = sw_off(row, chunk);
                ldsm4(ah[t][0], ah[t][1], ah[t][2], ah[t][3], stb + so);
                ldsm4(al[t][0], al[t][1], al[t][2], al[t][3], stb + OFF_ALO + so);
            }
            unsigned bh[4][2];
            unsigned bl[4][2];
            int p;
#pragma unroll
            for (p = 0; p < 2; ++p) {
                int row = wn * 32 + p * 16 + b_roff;
                int chunk = ks * 2 + b_coff;
                unsigned so = sw_off(row, chunk);
                unsigned r0, r1, r2, r3;
                ldsm4(r0, r1, r2, r3, stb + OFF_BHI + so);
                bh[p * 2][0] = r0;
                bh[p * 2][1] = r1;
                bh[p * 2 + 1][0] = r2;
                bh[p * 2 + 1][1] = r3;
                ldsm4(r0, r1, r2, r3, stb + OFF_BLO + so);
                bl[p * 2][0] = r0;
                bl[p * 2][1] = r1;
                bl[p * 2 + 1][0] = r2;
                bl[p * 2 + 1][1] = r3;
            }
#pragma unroll
            for (t = 0; t < 2; ++t) {
#pragma unroll
                for (j = 0; j < 4; ++j) {
                    mma16816(acc[t][j], ah[t][0], ah[t][1], ah[t][2], ah[t][3], bh[j][0], bh[j][1]);
                    mma16816(acc[t][j], ah[t][0], ah[t][1], ah[t][2], ah[t][3], bl[j][0], bl[j][1]);
                    mma16816(acc[t][j], al[t][0], al[t][1], al[t][2], al[t][3], bh[j][0], bh[j][1]);
                }
            }
        }

        __syncthreads();
        if (it + STAGES < NITER) {
            load_stage(smem, s, it + STAGES, tid, arow0, Bhi, Blo);
        } else {
            __pipeline_commit();
        }
    }

    float* dst = out;
    if (layer == 0) dst = (float*)g_Y;

    const int g = lane >> 2;
    const int tig = lane & 3;
#pragma unroll
    for (t = 0; t < 2; ++t) {
#pragma unroll
        for (j = 0; j < 4; ++j) {
            int col = wn * 32 + j * 8 + tig * 2;
            size_t row0 = arow0 + wm * 32 + t * 16 + g;
            size_t row1 = row0 + 8;
            float2 v0;
            float2 v1;
            v0.x = acc[t][j][0];
            v0.y = acc[t][j][1];
            v1.x = acc[t][j][2];
            v1.y = acc[t][j][3];
            if (col < 64) {
                v0.x = fmaxf(v0.x, 0.0f);
                v0.y = fmaxf(v0.y, 0.0f);
                v1.x = fmaxf(v1.x, 0.0f);
                v1.y = fmaxf(v1.y, 0.0f);
            }
            *reinterpret_cast<float2*>(dst + row0 * CD + col) = v0;
            *reinterpret_cast<float2*>(dst + row1 * CD + col) = v1;
        }
    }
}

extern "C" void kernel_launch(void* const* d_in, const int* in_sizes, int n_in,
                              void* d_out, int out_size)
{
    const float* A = (const float*)d_in[0];
    const float* F = (const float*)d_in[1];
    const float* G = (const float*)d_in[2];
    float* out = (float*)d_out;

    cudaFuncSetAttribute(gemm_kernel, cudaFuncAttributeMaxDynamicSharedMemorySize, SMEM_TOTAL);

    convA_kernel<<<2048, 256>>>(A);
    packX_kernel<<<(CD * NN) / 256, 256>>>(F, G);
    gemm_kernel<<<NN / 64, 256, SMEM_TOTAL>>>(0, out);
    packY_kernel<<<(CD * NN) / 256, 256>>>();
    gemm_kernel<<<NN / 64, 256, SMEM_TOTAL>>>(1, out);
}